// round 9
// baseline (speedup 1.0000x reference)
#include <cuda_runtime.h>

// Problem constants (fixed by the dataset)
#define NMAX   50000
#define CFEAT  256      // aggregation feature width (IN_C == HID == 256)
#define OUTC   128
#define EMAX   800000

// Scratch: __device__ globals (no cudaMalloc allowed)
__device__ float g_dinv[NMAX];                         // degree, then rsqrt(degree)
__device__ float g_bufA[(size_t)NMAX * CFEAT];         // xw, then h
__device__ float g_bufB[(size_t)NMAX * CFEAT];         // aggregation accumulator
__device__ int   g_esrc[EMAX];
__device__ int   g_edst[EMAX];
__device__ float g_enorm[EMAX];
__device__ int   g_is64;                               // edge_index dtype flag

// ---------------------------------------------------------------------------
// dtype detection: int64 indices in [0, N) have all-zero odd 32-bit words
// (little-endian). 64 samples -> false-positive probability ~ (2e-5)^64.
// ---------------------------------------------------------------------------
__global__ void k_detect(const int* __restrict__ w, int E) {
    if (threadIdx.x == 0 && blockIdx.x == 0) {
        int nsamp = 2 * E < 128 ? (2 * E) / 2 : 64;
        int all_zero = 1;
        for (int i = 0; i < nsamp; i++) {
            if (w[2 * i + 1] != 0) { all_zero = 0; break; }
        }
        g_is64 = all_zero;
    }
}

__device__ __forceinline__ int load_idx(const void* ei, long long pos, int is64) {
    if (is64) return (int)((const long long*)ei)[pos];
    return ((const int*)ei)[pos];
}

// ---------------------------------------------------------------------------
// degree / norm
// ---------------------------------------------------------------------------
__global__ void k_init_deg(int n) {
    int i = blockIdx.x * blockDim.x + threadIdx.x;
    if (i < n) g_dinv[i] = 1.0f;  // self-loop contributes 1
}

__global__ void k_count_deg(const void* __restrict__ ei, int E) {
    int e = blockIdx.x * blockDim.x + threadIdx.x;
    if (e >= E) return;
    int is64 = g_is64;
    int d = load_idx(ei, (long long)E + e, is64);   // dst = ei[1][e]
    atomicAdd(&g_dinv[d], 1.0f);
}

__global__ void k_dinv(int n) {
    int i = blockIdx.x * blockDim.x + threadIdx.x;
    if (i < n) g_dinv[i] = rsqrtf(g_dinv[i]);
}

// Pack src/dst to int32 and precompute per-edge norm = dinv[src]*dinv[dst]
__global__ void k_edge_prep(const void* __restrict__ ei, int E) {
    int e = blockIdx.x * blockDim.x + threadIdx.x;
    if (e >= E) return;
    int is64 = g_is64;
    int s = load_idx(ei, e, is64);
    int d = load_idx(ei, (long long)E + e, is64);
    g_esrc[e] = s;
    g_edst[e] = d;
    g_enorm[e] = g_dinv[s] * g_dinv[d];
}

// ---------------------------------------------------------------------------
// Core fp32 GEMM block routine: 128x128 tile, BK=16, 256 threads,
// 8x8 per thread, double-buffered smem. Computes the tile
// C[bm:bm+128, bn:bn+128] of A[M,K] @ B[K,Ncols] into acc.
// ---------------------------------------------------------------------------
__device__ __forceinline__ void sgemm_tile(
    const float* __restrict__ A, const float* __restrict__ B,
    int M, int K, int Ncols, int bm, int bn,
    float (&acc)[8][8],
    float (*As)[16][128], float (*Bs)[16][128])
{
    const int BK = 16;
    int tid = threadIdx.x;
    int tx = tid & 15;
    int ty = tid >> 4;

    // A tile: 128x16 = 512 float4, 2 per thread
    int ar0 = tid >> 2,          ac0 = (tid & 3) * 4;
    int ar1 = (tid + 256) >> 2,  ac1 = ((tid + 256) & 3) * 4;
    // B tile: 16x128 = 512 float4, 2 per thread
    int br0 = tid >> 5,          bc0 = (tid & 31) * 4;
    int br1 = (tid + 256) >> 5,  bc1 = ((tid + 256) & 31) * 4;

    float4 aR0, aR1, bR0, bR1;

    // prefetch tile kk=0
    {
        int g0 = bm + ar0, g1 = bm + ar1;
        aR0 = (g0 < M) ? *(const float4*)&A[(size_t)g0 * K + ac0] : make_float4(0,0,0,0);
        aR1 = (g1 < M) ? *(const float4*)&A[(size_t)g1 * K + ac1] : make_float4(0,0,0,0);
        bR0 = *(const float4*)&B[(size_t)br0 * Ncols + bn + bc0];
        bR1 = *(const float4*)&B[(size_t)br1 * Ncols + bn + bc1];
    }
    As[0][ac0 + 0][ar0] = aR0.x; As[0][ac0 + 1][ar0] = aR0.y;
    As[0][ac0 + 2][ar0] = aR0.z; As[0][ac0 + 3][ar0] = aR0.w;
    As[0][ac1 + 0][ar1] = aR1.x; As[0][ac1 + 1][ar1] = aR1.y;
    As[0][ac1 + 2][ar1] = aR1.z; As[0][ac1 + 3][ar1] = aR1.w;
    *(float4*)&Bs[0][br0][bc0] = bR0;
    *(float4*)&Bs[0][br1][bc1] = bR1;
    __syncthreads();

    int cur = 0;
    for (int kk = BK; kk <= K; kk += BK) {
        bool more = (kk < K);
        if (more) {
            int g0 = bm + ar0, g1 = bm + ar1;
            aR0 = (g0 < M) ? *(const float4*)&A[(size_t)g0 * K + kk + ac0] : make_float4(0,0,0,0);
            aR1 = (g1 < M) ? *(const float4*)&A[(size_t)g1 * K + kk + ac1] : make_float4(0,0,0,0);
            bR0 = *(const float4*)&B[(size_t)(kk + br0) * Ncols + bn + bc0];
            bR1 = *(const float4*)&B[(size_t)(kk + br1) * Ncols + bn + bc1];
        }

#pragma unroll
        for (int k = 0; k < BK; k++) {
            float a[8], b[8];
            *(float4*)&a[0] = *(float4*)&As[cur][k][ty * 8];
            *(float4*)&a[4] = *(float4*)&As[cur][k][ty * 8 + 4];
            *(float4*)&b[0] = *(float4*)&Bs[cur][k][tx * 8];
            *(float4*)&b[4] = *(float4*)&Bs[cur][k][tx * 8 + 4];
#pragma unroll
            for (int i = 0; i < 8; i++)
#pragma unroll
                for (int j = 0; j < 8; j++) acc[i][j] = fmaf(a[i], b[j], acc[i][j]);
        }

        if (more) {
            int nxt = cur ^ 1;
            As[nxt][ac0 + 0][ar0] = aR0.x; As[nxt][ac0 + 1][ar0] = aR0.y;
            As[nxt][ac0 + 2][ar0] = aR0.z; As[nxt][ac0 + 3][ar0] = aR0.w;
            As[nxt][ac1 + 0][ar1] = aR1.x; As[nxt][ac1 + 1][ar1] = aR1.y;
            As[nxt][ac1 + 2][ar1] = aR1.z; As[nxt][ac1 + 3][ar1] = aR1.w;
            *(float4*)&Bs[nxt][br0][bc0] = bR0;
            *(float4*)&Bs[nxt][br1][bc1] = bR1;
            __syncthreads();
            cur = nxt;
        }
    }
}

// ---------------------------------------------------------------------------
// GEMM1: xw = x @ W1 -> C, and C2 = dinv[row]^2 * xw (fused self-loop seed)
// grid: (Ncols/128, ceil(M/128))
// ---------------------------------------------------------------------------
__global__ __launch_bounds__(256) void k_sgemm1(
    const float* __restrict__ A, const float* __restrict__ B,
    float* __restrict__ Cmat, float* __restrict__ C2,
    int M, int K, int Ncols)
{
    __shared__ float As[2][16][128];
    __shared__ float Bs[2][16][128];
    int bm = blockIdx.y * 128;
    int bn = blockIdx.x * 128;
    int tx = threadIdx.x & 15, ty = threadIdx.x >> 4;

    float acc[8][8];
#pragma unroll
    for (int i = 0; i < 8; i++)
#pragma unroll
        for (int j = 0; j < 8; j++) acc[i][j] = 0.0f;

    sgemm_tile(A, B, M, K, Ncols, bm, bn, acc, As, Bs);

#pragma unroll
    for (int i = 0; i < 8; i++) {
        int r = bm + ty * 8 + i;
        if (r >= M) break;
        float s = g_dinv[r];
        float s2 = s * s;
#pragma unroll
        for (int j = 0; j < 8; j += 4) {
            int c = bn + tx * 8 + j;
            float4 v = make_float4(acc[i][j], acc[i][j + 1], acc[i][j + 2], acc[i][j + 3]);
            *(float4*)&Cmat[(size_t)r * Ncols + c] = v;
            float4 w = make_float4(v.x * s2, v.y * s2, v.z * s2, v.w * s2);
            *(float4*)&C2[(size_t)r * Ncols + c] = w;
        }
    }
}

// ---------------------------------------------------------------------------
// GEMM2 (dual): one launch computes BOTH mu and logstd.
// blockIdx.x selects {Wmu,bmu,Cmu} (0) or {Wls,bls,Cls} (1). Ncols = OUTC.
// grid: (2, ceil(M/128))
// ---------------------------------------------------------------------------
__global__ __launch_bounds__(256) void k_sgemm2(
    const float* __restrict__ A,
    const float* __restrict__ Wmu, const float* __restrict__ bmu, float* __restrict__ Cmu,
    const float* __restrict__ Wls, const float* __restrict__ bls, float* __restrict__ Cls,
    int M, int K)
{
    __shared__ float As[2][16][128];
    __shared__ float Bs[2][16][128];
    const float* B    = (blockIdx.x == 0) ? Wmu : Wls;
    const float* bias = (blockIdx.x == 0) ? bmu : bls;
    float*       C    = (blockIdx.x == 0) ? Cmu : Cls;

    int bm = blockIdx.y * 128;
    int tx = threadIdx.x & 15, ty = threadIdx.x >> 4;

    float acc[8][8];
#pragma unroll
    for (int i = 0; i < 8; i++)
#pragma unroll
        for (int j = 0; j < 8; j++) acc[i][j] = 0.0f;

    sgemm_tile(A, B, M, K, OUTC, bm, 0, acc, As, Bs);

#pragma unroll
    for (int i = 0; i < 8; i++) {
        int r = bm + ty * 8 + i;
        if (r >= M) break;
#pragma unroll
        for (int j = 0; j < 8; j += 4) {
            int c = tx * 8 + j;
            float4 v = make_float4(acc[i][j], acc[i][j + 1], acc[i][j + 2], acc[i][j + 3]);
            v.x += bias[c]; v.y += bias[c + 1]; v.z += bias[c + 2]; v.w += bias[c + 3];
            *(float4*)&C[(size_t)r * OUTC + c] = v;
        }
    }
}

// ---------------------------------------------------------------------------
// fused: h = relu(agg + b1) -> bufA ; bufB(in place) = dinv^2 * h
// ---------------------------------------------------------------------------
__global__ void k_bias_relu_self(const float* __restrict__ bias, int n) {
    size_t i = (size_t)blockIdx.x * blockDim.x + threadIdx.x;  // float4 index
    size_t total = (size_t)n * (CFEAT / 4);
    if (i >= total) return;
    int row = (int)(i >> 6);
    int c = (int)(i & 63) * 4;
    float4 v = ((const float4*)g_bufB)[i];
    float4 b = *(const float4*)&bias[c];
    v.x = fmaxf(v.x + b.x, 0.f);
    v.y = fmaxf(v.y + b.y, 0.f);
    v.z = fmaxf(v.z + b.z, 0.f);
    v.w = fmaxf(v.w + b.w, 0.f);
    ((float4*)g_bufA)[i] = v;       // h
    float s = g_dinv[row]; s = s * s;
    v.x *= s; v.y *= s; v.z *= s; v.w *= s;
    ((float4*)g_bufB)[i] = v;       // self-loop seed for next aggregation
}

// ---------------------------------------------------------------------------
// edge scatter-add: out[dst] += norm[e] * in[src], one warp per edge,
// grid-stride over edges. Scalar atomicAdd (RED.E.ADD.F32).
// ---------------------------------------------------------------------------
__global__ __launch_bounds__(256) void k_edge_agg(const float* __restrict__ in,
                                                  float* __restrict__ out, int E)
{
    int lane = threadIdx.x & 31;
    int warpsPerGrid = (gridDim.x * blockDim.x) >> 5;
    int warp0 = (int)(((size_t)blockIdx.x * blockDim.x + threadIdx.x) >> 5);
    for (int e = warp0; e < E; e += warpsPerGrid) {
        int s = g_esrc[e];
        int d = g_edst[e];
        float norm = g_enorm[e];
        const float4* ip = (const float4*)(in + (size_t)s * CFEAT);
        float* op = out + (size_t)d * CFEAT;
        float4 v0 = ip[lane];
        float4 v1 = ip[lane + 32];
        float* p0 = op + lane * 4;
        atomicAdd(p0 + 0, v0.x * norm);
        atomicAdd(p0 + 1, v0.y * norm);
        atomicAdd(p0 + 2, v0.z * norm);
        atomicAdd(p0 + 3, v0.w * norm);
        float* p1 = op + (lane + 32) * 4;
        atomicAdd(p1 + 0, v1.x * norm);
        atomicAdd(p1 + 1, v1.y * norm);
        atomicAdd(p1 + 2, v1.z * norm);
        atomicAdd(p1 + 3, v1.w * norm);
    }
}

// ---------------------------------------------------------------------------
// launch
// ---------------------------------------------------------------------------
extern "C" void kernel_launch(void* const* d_in, const int* in_sizes, int n_in,
                              void* d_out, int out_size)
{
    const float* x    = (const float*)d_in[0];
    const void*  ei   = d_in[1];                 // int32 OR int64 — detected on device
    const float* W1   = (const float*)d_in[2];
    const float* b1   = (const float*)d_in[3];
    const float* Wmu  = (const float*)d_in[4];
    const float* bmu  = (const float*)d_in[5];
    const float* Wls  = (const float*)d_in[6];
    const float* bls  = (const float*)d_in[7];

    int n = in_sizes[0] / CFEAT;       // 50000
    int E = in_sizes[1] / 2;           // 800000

    float* out_mu = (float*)d_out;
    float* out_ls = out_mu + (size_t)n * OUTC;

    float *bufA, *bufB;
    cudaGetSymbolAddress((void**)&bufA, g_bufA);
    cudaGetSymbolAddress((void**)&bufB, g_bufB);

    // 0) detect edge_index dtype (writes g_is64)
    k_detect<<<1, 32>>>((const int*)ei, E);

    // 1) degree -> dinv -> per-edge norm
    k_init_deg<<<(n + 255) / 256, 256>>>(n);
    k_count_deg<<<(E + 255) / 256, 256>>>(ei, E);
    k_dinv<<<(n + 255) / 256, 256>>>(n);
    k_edge_prep<<<(E + 255) / 256, 256>>>(ei, E);

    // Edge-agg grid: one warp per edge (grid-stride handles any E)
    int eblocks = (E + 7) / 8;   // 8 warps per 256-thread block

    // 2) xw = x @ W1 -> bufA, and bufB = dinv^2 * xw (fused self-loop seed)
    {
        dim3 grid(CFEAT / 128, (n + 127) / 128);
        k_sgemm1<<<grid, 256>>>(x, W1, bufA, bufB, n, CFEAT, CFEAT);
    }

    // 3) agg1 += edges  (bufB accumulates A_norm @ xw)
    k_edge_agg<<<eblocks, 256>>>(bufA, bufB, E);

    // 4) h = relu(agg1 + b1) -> bufA ; bufB = dinv^2 * h (in place)
    size_t v4 = (size_t)n * (CFEAT / 4);
    int vblocks = (int)((v4 + 255) / 256);
    k_bias_relu_self<<<vblocks, 256>>>(b1, n);

    // 5) g = A_norm @ h -> bufB (self-loop part already seeded in bufB)
    k_edge_agg<<<eblocks, 256>>>(bufA, bufB, E);

    // 6) mu = g @ Wmu + bmu ; logstd = g @ Wls + bls  (one merged launch)
    {
        dim3 grid(2, (n + 127) / 128);
        k_sgemm2<<<grid, 256>>>(bufB, Wmu, bmu, out_mu, Wls, bls, out_ls, n, CFEAT);
    }
}

// round 14
// speedup vs baseline: 2.3513x; 2.3513x over previous
#include <cuda_runtime.h>

// Problem constants (fixed by the dataset)
#define NMAX   50000
#define CFEAT  256      // aggregation feature width (IN_C == HID == 256)
#define OUTC   128
#define EMAX   800000

// Scratch: __device__ globals (no cudaMalloc allowed)
__device__ float  g_dinv[NMAX];                        // rsqrt(1+deg)
__device__ int    g_count[NMAX];                       // in-degree (excl self)
__device__ int    g_cursor[NMAX];                      // scatter cursors
__device__ int    g_rowstart[NMAX + 1];                // CSR row offsets
__device__ float2 g_cedge[EMAX];                       // (src as int bits, norm)
__device__ float  g_bufA[(size_t)NMAX * CFEAT];        // xw, then g
__device__ float  g_bufB[(size_t)NMAX * CFEAT];        // h
__device__ int    g_is64;                              // edge_index dtype flag

// ---------------------------------------------------------------------------
// dtype detection: int64 indices in [0, N) have all-zero odd 32-bit words
// (little-endian). 64 samples -> false-positive probability ~ (2e-5)^64.
// ---------------------------------------------------------------------------
__global__ void k_detect(const int* __restrict__ w, int E) {
    if (threadIdx.x == 0 && blockIdx.x == 0) {
        int nsamp = 2 * E < 128 ? (2 * E) / 2 : 64;
        int all_zero = 1;
        for (int i = 0; i < nsamp; i++) {
            if (w[2 * i + 1] != 0) { all_zero = 0; break; }
        }
        g_is64 = all_zero;
    }
}

__device__ __forceinline__ int load_idx(const void* ei, long long pos, int is64) {
    if (is64) return (int)((const long long*)ei)[pos];
    return ((const int*)ei)[pos];
}

// ---------------------------------------------------------------------------
// degree / norm / CSR build
// ---------------------------------------------------------------------------
__global__ void k_zero(int n) {
    int i = blockIdx.x * blockDim.x + threadIdx.x;
    if (i < n) { g_count[i] = 0; g_cursor[i] = 0; }
}

__global__ void k_count(const void* __restrict__ ei, int E) {
    int e = blockIdx.x * blockDim.x + threadIdx.x;
    if (e >= E) return;
    int d = load_idx(ei, (long long)E + e, g_is64);   // dst = ei[1][e]
    atomicAdd(&g_count[d], 1);
}

__global__ void k_dinv(int n) {
    int i = blockIdx.x * blockDim.x + threadIdx.x;
    if (i < n) g_dinv[i] = rsqrtf((float)g_count[i] + 1.0f);  // +1 self-loop
}

// single-block exclusive scan of g_count -> g_rowstart (n up to ~50K)
__global__ void k_scan(int n) {
    __shared__ int ssum[1024];
    int t = threadIdx.x;
    int per = (n + 1023) / 1024;
    int beg = t * per;
    int end = beg + per < n ? beg + per : n;
    int sum = 0;
    for (int i = beg; i < end; i++) sum += g_count[i];
    ssum[t] = sum;
    __syncthreads();
    // Hillis-Steele inclusive scan over 1024 partials
    for (int off = 1; off < 1024; off <<= 1) {
        int v = (t >= off) ? ssum[t - off] : 0;
        __syncthreads();
        ssum[t] += v;
        __syncthreads();
    }
    int run = ssum[t] - sum;   // exclusive prefix for this chunk
    for (int i = beg; i < end; i++) { g_rowstart[i] = run; run += g_count[i]; }
    if (end == n) g_rowstart[n] = run;   // total (benign multi-write, same value)
}

__global__ void k_scatter(const void* __restrict__ ei, int E) {
    int e = blockIdx.x * blockDim.x + threadIdx.x;
    if (e >= E) return;
    int is64 = g_is64;
    int s = load_idx(ei, e, is64);
    int d = load_idx(ei, (long long)E + e, is64);
    float norm = g_dinv[s] * g_dinv[d];
    int pos = g_rowstart[d] + atomicAdd(&g_cursor[d], 1);
    g_cedge[pos] = make_float2(__int_as_float(s), norm);
}

// ---------------------------------------------------------------------------
// Core fp32 GEMM block routine: 128x128 tile, BK=16, 256 threads,
// 8x8 per thread, double-buffered smem.
// ---------------------------------------------------------------------------
__device__ __forceinline__ void sgemm_tile(
    const float* __restrict__ A, const float* __restrict__ B,
    int M, int K, int Ncols, int bm, int bn,
    float (&acc)[8][8],
    float (*As)[16][128], float (*Bs)[16][128])
{
    const int BK = 16;
    int tid = threadIdx.x;
    int tx = tid & 15;
    int ty = tid >> 4;

    int ar0 = tid >> 2,          ac0 = (tid & 3) * 4;
    int ar1 = (tid + 256) >> 2,  ac1 = ((tid + 256) & 3) * 4;
    int br0 = tid >> 5,          bc0 = (tid & 31) * 4;
    int br1 = (tid + 256) >> 5,  bc1 = ((tid + 256) & 31) * 4;

    float4 aR0, aR1, bR0, bR1;

    {
        int g0 = bm + ar0, g1 = bm + ar1;
        aR0 = (g0 < M) ? *(const float4*)&A[(size_t)g0 * K + ac0] : make_float4(0,0,0,0);
        aR1 = (g1 < M) ? *(const float4*)&A[(size_t)g1 * K + ac1] : make_float4(0,0,0,0);
        bR0 = *(const float4*)&B[(size_t)br0 * Ncols + bn + bc0];
        bR1 = *(const float4*)&B[(size_t)br1 * Ncols + bn + bc1];
    }
    As[0][ac0 + 0][ar0] = aR0.x; As[0][ac0 + 1][ar0] = aR0.y;
    As[0][ac0 + 2][ar0] = aR0.z; As[0][ac0 + 3][ar0] = aR0.w;
    As[0][ac1 + 0][ar1] = aR1.x; As[0][ac1 + 1][ar1] = aR1.y;
    As[0][ac1 + 2][ar1] = aR1.z; As[0][ac1 + 3][ar1] = aR1.w;
    *(float4*)&Bs[0][br0][bc0] = bR0;
    *(float4*)&Bs[0][br1][bc1] = bR1;
    __syncthreads();

    int cur = 0;
    for (int kk = BK; kk <= K; kk += BK) {
        bool more = (kk < K);
        if (more) {
            int g0 = bm + ar0, g1 = bm + ar1;
            aR0 = (g0 < M) ? *(const float4*)&A[(size_t)g0 * K + kk + ac0] : make_float4(0,0,0,0);
            aR1 = (g1 < M) ? *(const float4*)&A[(size_t)g1 * K + kk + ac1] : make_float4(0,0,0,0);
            bR0 = *(const float4*)&B[(size_t)(kk + br0) * Ncols + bn + bc0];
            bR1 = *(const float4*)&B[(size_t)(kk + br1) * Ncols + bn + bc1];
        }

#pragma unroll
        for (int k = 0; k < BK; k++) {
            float a[8], b[8];
            *(float4*)&a[0] = *(float4*)&As[cur][k][ty * 8];
            *(float4*)&a[4] = *(float4*)&As[cur][k][ty * 8 + 4];
            *(float4*)&b[0] = *(float4*)&Bs[cur][k][tx * 8];
            *(float4*)&b[4] = *(float4*)&Bs[cur][k][tx * 8 + 4];
#pragma unroll
            for (int i = 0; i < 8; i++)
#pragma unroll
                for (int j = 0; j < 8; j++) acc[i][j] = fmaf(a[i], b[j], acc[i][j]);
        }

        if (more) {
            int nxt = cur ^ 1;
            As[nxt][ac0 + 0][ar0] = aR0.x; As[nxt][ac0 + 1][ar0] = aR0.y;
            As[nxt][ac0 + 2][ar0] = aR0.z; As[nxt][ac0 + 3][ar0] = aR0.w;
            As[nxt][ac1 + 0][ar1] = aR1.x; As[nxt][ac1 + 1][ar1] = aR1.y;
            As[nxt][ac1 + 2][ar1] = aR1.z; As[nxt][ac1 + 3][ar1] = aR1.w;
            *(float4*)&Bs[nxt][br0][bc0] = bR0;
            *(float4*)&Bs[nxt][br1][bc1] = bR1;
            __syncthreads();
            cur = nxt;
        }
    }
}

// ---------------------------------------------------------------------------
// GEMM1: xw = x @ W1 -> C.  grid: (Ncols/128, ceil(M/128))
// ---------------------------------------------------------------------------
__global__ __launch_bounds__(256) void k_sgemm1(
    const float* __restrict__ A, const float* __restrict__ B,
    float* __restrict__ Cmat, int M, int K, int Ncols)
{
    __shared__ float As[2][16][128];
    __shared__ float Bs[2][16][128];
    int bm = blockIdx.y * 128;
    int bn = blockIdx.x * 128;
    int tx = threadIdx.x & 15, ty = threadIdx.x >> 4;

    float acc[8][8];
#pragma unroll
    for (int i = 0; i < 8; i++)
#pragma unroll
        for (int j = 0; j < 8; j++) acc[i][j] = 0.0f;

    sgemm_tile(A, B, M, K, Ncols, bm, bn, acc, As, Bs);

#pragma unroll
    for (int i = 0; i < 8; i++) {
        int r = bm + ty * 8 + i;
        if (r >= M) break;
#pragma unroll
        for (int j = 0; j < 8; j += 4) {
            int c = bn + tx * 8 + j;
            float4 v = make_float4(acc[i][j], acc[i][j + 1], acc[i][j + 2], acc[i][j + 3]);
            *(float4*)&Cmat[(size_t)r * Ncols + c] = v;
        }
    }
}

// ---------------------------------------------------------------------------
// GEMM2 (dual): one launch computes BOTH mu and logstd.
// blockIdx.x selects weights/bias/output. grid: (2, ceil(M/128))
// ---------------------------------------------------------------------------
__global__ __launch_bounds__(256) void k_sgemm2(
    const float* __restrict__ A,
    const float* __restrict__ Wmu, const float* __restrict__ bmu, float* __restrict__ Cmu,
    const float* __restrict__ Wls, const float* __restrict__ bls, float* __restrict__ Cls,
    int M, int K)
{
    __shared__ float As[2][16][128];
    __shared__ float Bs[2][16][128];
    const float* B    = (blockIdx.x == 0) ? Wmu : Wls;
    const float* bias = (blockIdx.x == 0) ? bmu : bls;
    float*       C    = (blockIdx.x == 0) ? Cmu : Cls;

    int bm = blockIdx.y * 128;
    int tx = threadIdx.x & 15, ty = threadIdx.x >> 4;

    float acc[8][8];
#pragma unroll
    for (int i = 0; i < 8; i++)
#pragma unroll
        for (int j = 0; j < 8; j++) acc[i][j] = 0.0f;

    sgemm_tile(A, B, M, K, OUTC, bm, 0, acc, As, Bs);

#pragma unroll
    for (int i = 0; i < 8; i++) {
        int r = bm + ty * 8 + i;
        if (r >= M) break;
#pragma unroll
        for (int j = 0; j < 8; j += 4) {
            int c = tx * 8 + j;
            float4 v = make_float4(acc[i][j], acc[i][j + 1], acc[i][j + 2], acc[i][j + 3]);
            v.x += bias[c]; v.y += bias[c + 1]; v.z += bias[c + 2]; v.w += bias[c + 3];
            *(float4*)&C[(size_t)r * OUTC + c] = v;
        }
    }
}

// ---------------------------------------------------------------------------
// Pull-mode aggregation: one warp per dst node, no atomics, 4-edge ILP.
// out[d] = dinv[d]^2 * in[d] + sum_{(s->d)} norm * in[s]   (+bias, relu opt.)
// Lane L owns columns [4L, 4L+4) and [128+4L, 128+4L+4).
// ---------------------------------------------------------------------------
#define ACC_FMA(nv, r0, r1)                                             \
    do {                                                                \
        acc0.x = fmaf(nv, (r0).x, acc0.x); acc0.y = fmaf(nv, (r0).y, acc0.y); \
        acc0.z = fmaf(nv, (r0).z, acc0.z); acc0.w = fmaf(nv, (r0).w, acc0.w); \
        acc1.x = fmaf(nv, (r1).x, acc1.x); acc1.y = fmaf(nv, (r1).y, acc1.y); \
        acc1.z = fmaf(nv, (r1).z, acc1.z); acc1.w = fmaf(nv, (r1).w, acc1.w); \
    } while (0)

template <int RELU>
__global__ __launch_bounds__(256) void k_pull(const float* __restrict__ in,
                                              float* __restrict__ out,
                                              const float* __restrict__ bias,
                                              int n)
{
    int lane = threadIdx.x & 31;
    int warpsPerGrid = (gridDim.x * blockDim.x) >> 5;
    int warp0 = (blockIdx.x * blockDim.x + threadIdx.x) >> 5;

    for (int d = warp0; d < n; d += warpsPerGrid) {
        int beg = g_rowstart[d];
        int end = g_rowstart[d + 1];
        float dv = g_dinv[d];
        float s2 = dv * dv;

        const float4* sp = (const float4*)(in + (size_t)d * CFEAT);
        float4 v0 = sp[lane];
        float4 v1 = sp[lane + 32];
        float4 acc0 = make_float4(v0.x * s2, v0.y * s2, v0.z * s2, v0.w * s2);
        float4 acc1 = make_float4(v1.x * s2, v1.y * s2, v1.z * s2, v1.w * s2);

        int p = beg;
        // 4-edge unroll: 8 independent LDG.128 + 4 LDG.64 in flight per iter
        for (; p + 3 < end; p += 4) {
            float2 e0 = g_cedge[p];
            float2 e1 = g_cedge[p + 1];
            float2 e2 = g_cedge[p + 2];
            float2 e3 = g_cedge[p + 3];
            const float4* i0 = (const float4*)(in + (size_t)__float_as_int(e0.x) * CFEAT);
            const float4* i1 = (const float4*)(in + (size_t)__float_as_int(e1.x) * CFEAT);
            const float4* i2 = (const float4*)(in + (size_t)__float_as_int(e2.x) * CFEAT);
            const float4* i3 = (const float4*)(in + (size_t)__float_as_int(e3.x) * CFEAT);
            float4 a0 = i0[lane], a1 = i0[lane + 32];
            float4 b0 = i1[lane], b1 = i1[lane + 32];
            float4 c0 = i2[lane], c1 = i2[lane + 32];
            float4 d0 = i3[lane], d1 = i3[lane + 32];
            ACC_FMA(e0.y, a0, a1);
            ACC_FMA(e1.y, b0, b1);
            ACC_FMA(e2.y, c0, c1);
            ACC_FMA(e3.y, d0, d1);
        }
        for (; p < end; p++) {
            float2 e0 = g_cedge[p];
            const float4* i0 = (const float4*)(in + (size_t)__float_as_int(e0.x) * CFEAT);
            float4 a0 = i0[lane], a1 = i0[lane + 32];
            ACC_FMA(e0.y, a0, a1);
        }

        if (RELU) {
            float4 b0 = *(const float4*)&bias[lane * 4];
            float4 b1 = *(const float4*)&bias[128 + lane * 4];
            acc0.x = fmaxf(acc0.x + b0.x, 0.f); acc0.y = fmaxf(acc0.y + b0.y, 0.f);
            acc0.z = fmaxf(acc0.z + b0.z, 0.f); acc0.w = fmaxf(acc0.w + b0.w, 0.f);
            acc1.x = fmaxf(acc1.x + b1.x, 0.f); acc1.y = fmaxf(acc1.y + b1.y, 0.f);
            acc1.z = fmaxf(acc1.z + b1.z, 0.f); acc1.w = fmaxf(acc1.w + b1.w, 0.f);
        }

        float4* op = (float4*)(out + (size_t)d * CFEAT);
        op[lane] = acc0;
        op[lane + 32] = acc1;
    }
}

// ---------------------------------------------------------------------------
// launch
// ---------------------------------------------------------------------------
extern "C" void kernel_launch(void* const* d_in, const int* in_sizes, int n_in,
                              void* d_out, int out_size)
{
    const float* x    = (const float*)d_in[0];
    const void*  ei   = d_in[1];                 // int32 OR int64 — detected on device
    const float* W1   = (const float*)d_in[2];
    const float* b1   = (const float*)d_in[3];
    const float* Wmu  = (const float*)d_in[4];
    const float* bmu  = (const float*)d_in[5];
    const float* Wls  = (const float*)d_in[6];
    const float* bls  = (const float*)d_in[7];

    int n = in_sizes[0] / CFEAT;       // 50000
    int E = in_sizes[1] / 2;           // 800000

    float* out_mu = (float*)d_out;
    float* out_ls = out_mu + (size_t)n * OUTC;

    float *bufA, *bufB;
    cudaGetSymbolAddress((void**)&bufA, g_bufA);
    cudaGetSymbolAddress((void**)&bufB, g_bufB);

    // 0) dtype detect + CSR build
    k_detect<<<1, 32>>>((const int*)ei, E);
    k_zero<<<(n + 255) / 256, 256>>>(n);
    k_count<<<(E + 255) / 256, 256>>>(ei, E);
    k_dinv<<<(n + 255) / 256, 256>>>(n);
    k_scan<<<1, 1024>>>(n);
    k_scatter<<<(E + 255) / 256, 256>>>(ei, E);

    // 1) xw = x @ W1 -> bufA
    {
        dim3 grid(CFEAT / 128, (n + 127) / 128);
        k_sgemm1<<<grid, 256>>>(x, W1, bufA, n, CFEAT, CFEAT);
    }

    // 2) h = relu(A_norm @ xw + b1) -> bufB   (pull, no atomics)
    int pblocks = (n + 7) / 8;    // 8 warps (nodes) per 256-thread block
    k_pull<1><<<pblocks, 256>>>(bufA, bufB, b1, n);

    // 3) g = A_norm @ h -> bufA
    k_pull<0><<<pblocks, 256>>>(bufB, bufA, nullptr, n);

    // 4) mu = g @ Wmu + bmu ; logstd = g @ Wls + bls  (one merged launch)
    {
        dim3 grid(2, (n + 127) / 128);
        k_sgemm2<<<grid, 256>>>(bufA, Wmu, bmu, out_mu, Wls, bls, out_ls, n, CFEAT);
    }
}